// round 1
// baseline (speedup 1.0000x reference)
#include <cuda_runtime.h>
#include <math.h>

#define BATCH 8
#define HH 720
#define WW 1280
#define HW (HH * WW)
#define NPIX (BATCH * HW)

// Scratch accumulators (no cudaMalloc allowed).
__device__ float g_cnt[NPIX];
__device__ float g_ox[NPIX];
__device__ float g_oy[NPIX];

// ---------------------------------------------------------------------------
// Kernel 1: zero the three accumulator planes (float4 vectorized).
// NPIX = 7,372,800 divisible by 4 -> 1,843,200 float4 per plane.
// ---------------------------------------------------------------------------
__global__ void zero_kernel() {
    const int n4 = NPIX / 4;
    int i = blockIdx.x * blockDim.x + threadIdx.x;
    float4 z = make_float4(0.f, 0.f, 0.f, 0.f);
    for (int k = i; k < n4; k += gridDim.x * blockDim.x) {
        reinterpret_cast<float4*>(g_cnt)[k] = z;
        reinterpret_cast<float4*>(g_ox)[k]  = z;
        reinterpret_cast<float4*>(g_oy)[k]  = z;
    }
}

// ---------------------------------------------------------------------------
// Kernel 2: scatter. One thread per source pixel. Invalid targets contribute
// exactly zero in the reference (w = 0), so skip them entirely.
// ---------------------------------------------------------------------------
__global__ void scatter_kernel(const float* __restrict__ flow,
                               const float* __restrict__ depth) {
    int i = blockIdx.x * blockDim.x + threadIdx.x;
    if (i >= NPIX) return;

    int b = i / HW;
    int p = i - b * HW;
    int y = p / WW;
    int x = p - y * WW;

    float fx = flow[(size_t)b * 2 * HW + p];
    float fy = flow[(size_t)b * 2 * HW + HW + p];
    float d  = depth[i];

    float x2 = (float)x + fx;
    float y2 = (float)y + fy;

    if (!(x2 >= 0.f && x2 <= (float)(WW - 1) &&
          y2 >= 0.f && y2 <= (float)(HH - 1)))
        return;

    int xL = (int)floorf(x2);
    int yT = (int)floorf(y2);
    int xR = min(xL + 1, WW - 1);
    int yB = min(yT + 1, HH - 1);

    float wx = -fx * d;
    float wy = -fy * d;

    int base = b * HW;
    int i00 = base + yT * WW + xL;
    int i01 = base + yT * WW + xR;
    int i10 = base + yB * WW + xL;
    int i11 = base + yB * WW + xR;

    atomicAdd(&g_cnt[i00], d);  atomicAdd(&g_ox[i00], wx);  atomicAdd(&g_oy[i00], wy);
    atomicAdd(&g_cnt[i01], d);  atomicAdd(&g_ox[i01], wx);  atomicAdd(&g_oy[i01], wy);
    atomicAdd(&g_cnt[i10], d);  atomicAdd(&g_ox[i10], wx);  atomicAdd(&g_oy[i10], wy);
    atomicAdd(&g_cnt[i11], d);  atomicAdd(&g_ox[i11], wx);  atomicAdd(&g_oy[i11], wy);
}

// ---------------------------------------------------------------------------
// Kernel 3: normalize and write output in (B, 2, H, W) layout.
// ---------------------------------------------------------------------------
__global__ void normalize_kernel(float* __restrict__ out) {
    int i = blockIdx.x * blockDim.x + threadIdx.x;
    if (i >= NPIX) return;

    float c = g_cnt[i];
    float ox = 0.f, oy = 0.f;
    if (c > 0.f) {
        float inv = 1.f / c;
        ox = g_ox[i] * inv;
        oy = g_oy[i] * inv;
    }

    int b = i / HW;
    int p = i - b * HW;
    out[(size_t)b * 2 * HW + p]      = ox;
    out[(size_t)b * 2 * HW + HW + p] = oy;
}

extern "C" void kernel_launch(void* const* d_in, const int* in_sizes, int n_in,
                              void* d_out, int out_size) {
    const float* flow  = (const float*)d_in[0];   // (B, 2, H, W)
    const float* depth = (const float*)d_in[1];   // (B, 1, H, W)
    float* out = (float*)d_out;                   // (B, 2, H, W)

    (void)in_sizes; (void)n_in; (void)out_size;

    const int threads = 256;

    // Zero accumulators: grid-stride over NPIX/4 float4 elements.
    int zero_blocks = 1480;  // 10 * 148 SMs, grid-stride
    zero_kernel<<<zero_blocks, threads>>>();

    int blocks = (NPIX + threads - 1) / threads;
    scatter_kernel<<<blocks, threads>>>(flow, depth);
    normalize_kernel<<<blocks, threads>>>(out);
}

// round 2
// speedup vs baseline: 1.5174x; 1.5174x over previous
#include <cuda_runtime.h>
#include <math.h>

#define BATCH 8
#define HH 720
#define WW 1280
#define HW (HH * WW)
#define NPIX (BATCH * HW)

// Packed accumulator: (cnt, ox, oy, pad). 16B aligned for red.global.add.v4.f32.
__device__ float4 g_acc[NPIX];

// ---------------------------------------------------------------------------
// Kernel 1: zero the accumulator plane (float4 stores, grid-stride).
// ---------------------------------------------------------------------------
__global__ void zero_kernel() {
    float4 z = make_float4(0.f, 0.f, 0.f, 0.f);
    int stride = gridDim.x * blockDim.x;
    for (int k = blockIdx.x * blockDim.x + threadIdx.x; k < NPIX; k += stride) {
        g_acc[k] = z;
    }
}

// ---------------------------------------------------------------------------
// Kernel 2: scatter. One thread per source pixel; 4 vector reductions
// (one per bilinear corner) instead of 12 scalar atomics.
// ---------------------------------------------------------------------------
__device__ __forceinline__ void red_add_v4(float4* addr, float a, float b, float c) {
    asm volatile(
        "red.global.add.v4.f32 [%0], {%1, %2, %3, %4};"
        :: "l"(addr), "f"(a), "f"(b), "f"(c), "f"(0.0f)
        : "memory");
}

__global__ void scatter_kernel(const float* __restrict__ flow,
                               const float* __restrict__ depth) {
    int i = blockIdx.x * blockDim.x + threadIdx.x;
    if (i >= NPIX) return;

    int b = i / HW;
    int p = i - b * HW;
    int y = p / WW;
    int x = p - y * WW;

    float fx = flow[(size_t)b * 2 * HW + p];
    float fy = flow[(size_t)b * 2 * HW + HW + p];
    float d  = depth[i];

    float x2 = (float)x + fx;
    float y2 = (float)y + fy;

    if (!(x2 >= 0.f && x2 <= (float)(WW - 1) &&
          y2 >= 0.f && y2 <= (float)(HH - 1)))
        return;

    int xL = (int)floorf(x2);
    int yT = (int)floorf(y2);
    int xR = min(xL + 1, WW - 1);
    int yB = min(yT + 1, HH - 1);

    float wx = -fx * d;
    float wy = -fy * d;

    int base = b * HW;
    int rT = base + yT * WW;
    int rB = base + yB * WW;

    red_add_v4(&g_acc[rT + xL], d, wx, wy);
    red_add_v4(&g_acc[rT + xR], d, wx, wy);
    red_add_v4(&g_acc[rB + xL], d, wx, wy);
    red_add_v4(&g_acc[rB + xR], d, wx, wy);
}

// ---------------------------------------------------------------------------
// Kernel 3: normalize and write output in (B, 2, H, W) layout.
// One LDG.128 per pixel.
// ---------------------------------------------------------------------------
__global__ void normalize_kernel(float* __restrict__ out) {
    int i = blockIdx.x * blockDim.x + threadIdx.x;
    if (i >= NPIX) return;

    float4 a = g_acc[i];
    float ox = 0.f, oy = 0.f;
    if (a.x > 0.f) {
        float inv = 1.f / a.x;
        ox = a.y * inv;
        oy = a.z * inv;
    }

    int b = i / HW;
    int p = i - b * HW;
    out[(size_t)b * 2 * HW + p]      = ox;
    out[(size_t)b * 2 * HW + HW + p] = oy;
}

extern "C" void kernel_launch(void* const* d_in, const int* in_sizes, int n_in,
                              void* d_out, int out_size) {
    const float* flow  = (const float*)d_in[0];   // (B, 2, H, W)
    const float* depth = (const float*)d_in[1];   // (B, 1, H, W)
    float* out = (float*)d_out;                   // (B, 2, H, W)

    (void)in_sizes; (void)n_in; (void)out_size;

    const int threads = 256;

    zero_kernel<<<1480, threads>>>();

    int blocks = (NPIX + threads - 1) / threads;
    scatter_kernel<<<blocks, threads>>>(flow, depth);
    normalize_kernel<<<blocks, threads>>>(out);
}